// round 5
// baseline (speedup 1.0000x reference)
#include <cuda_runtime.h>
#include <cuda_bf16.h>

#define HID 256
#define GAMMA_F 12.0f
#define BATCH 8

typedef unsigned long long u64;

__device__ float g_scores[BATCH * 100000];  // S[e*8+b], 3.2MB (L2-resident)

__device__ __forceinline__ u64 ffma2(u64 a, u64 b, u64 c) {
    u64 d;
    asm("fma.rn.f32x2 %0, %1, %2, %3;" : "=l"(d) : "l"(a), "l"(b), "l"(c));
    return d;
}
__device__ __forceinline__ u64 fadd2(u64 a, u64 b) {
    u64 d;
    asm("add.rn.f32x2 %0, %1, %2;" : "=l"(d) : "l"(a), "l"(b));
    return d;
}
__device__ __forceinline__ u64 pack2(float lo, float hi) {
    u64 d;
    asm("mov.b64 %0, {%1, %2};" : "=l"(d) : "f"(lo), "f"(hi));
    return d;
}
__device__ __forceinline__ float2 unpack2(u64 v) {
    float2 r;
    asm("mov.b64 {%0, %1}, %2;" : "=f"(r.x), "=f"(r.y) : "l"(v));
    return r;
}

#define ABSMASK2 0x7FFFFFFF7FFFFFFFULL
#define NEG1X2   0xBF800000BF800000ULL

// ---------------------------------------------------------------------------
// Phase 1: stream entity table once; score all 8 hr vectors per row.
// Warp per contiguous row chunk; 4 rows in flight (2-row groups, prefetched).
// ---------------------------------------------------------------------------
__global__ void __launch_bounds__(256, 2)
score_all_kernel(const float* __restrict__ ent,
                 const float* __restrict__ rel,
                 const int*   __restrict__ pos,
                 float*       __restrict__ scores,
                 int ne)
{
    const int lane = threadIdx.x & 31;
    const int warp = threadIdx.x >> 5;

    // hr = head + relation, packed f32x2: hr2[b][p] = lane dims (p*2, p*2+1).
    u64 hr2[BATCH][4];
#pragma unroll
    for (int b = 0; b < BATCH; b++) {
        const int hidx = pos[b * 3 + 0];
        const int ridx = pos[b * 3 + 1];
        const float4* h4 = reinterpret_cast<const float4*>(ent + (size_t)hidx * HID);
        const float4* r4 = reinterpret_cast<const float4*>(rel + (size_t)ridx * HID);
        float4 h0 = h4[lane * 2], h1 = h4[lane * 2 + 1];
        float4 r0 = r4[lane * 2], r1 = r4[lane * 2 + 1];
        hr2[b][0] = pack2(h0.x + r0.x, h0.y + r0.y);
        hr2[b][1] = pack2(h0.z + r0.z, h0.w + r0.w);
        hr2[b][2] = pack2(h1.x + r1.x, h1.y + r1.y);
        hr2[b][3] = pack2(h1.z + r1.z, h1.w + r1.w);
    }

    const bool hi16 = (lane & 16) != 0;
    const bool hi8  = (lane & 8)  != 0;
    const bool hi4  = (lane & 4)  != 0;

    // Contiguous chunk per warp.
    const int gw = blockIdx.x * (blockDim.x >> 5) + warp;
    const int W  = gridDim.x * (blockDim.x >> 5);
    const int base  = ne / W;
    const int rem   = ne % W;
    const int start = gw * base + (gw < rem ? gw : rem);
    const int end   = start + base + (gw < rem ? 1 : 0);

    auto loadrow = [&](int row, u64* buf) {
        const ulonglong2* p = reinterpret_cast<const ulonglong2*>(ent + (size_t)row * HID);
        ulonglong2 x = p[lane * 2], y = p[lane * 2 + 1];
        buf[0] = x.x; buf[1] = x.y; buf[2] = y.x; buf[3] = y.y;
    };

    auto compute_store = [&](const u64* e2, int row) {
        float v[BATCH];
#pragma unroll
        for (int b = 0; b < BATCH; b++) {
            u64 acc = 0;
#pragma unroll
            for (int p = 0; p < 4; p++) {
                const u64 d2 = ffma2(e2[p], NEG1X2, hr2[b][p]);  // hr - e
                acc = fadd2(acc, d2 & ABSMASK2);                  // += |d|
            }
            const float2 a = unpack2(acc);
            v[b] = a.x + a.y;
        }
        // Folding reduction: lane group (lane>>2) ends with batch (lane>>2).
#pragma unroll
        for (int j = 0; j < 4; j++) {
            const float send = hi16 ? v[j] : v[j + 4];
            const float recv = __shfl_xor_sync(0xFFFFFFFFu, send, 16);
            v[j] = (hi16 ? v[j + 4] : v[j]) + recv;
        }
#pragma unroll
        for (int j = 0; j < 2; j++) {
            const float send = hi8 ? v[j] : v[j + 2];
            const float recv = __shfl_xor_sync(0xFFFFFFFFu, send, 8);
            v[j] = (hi8 ? v[j + 2] : v[j]) + recv;
        }
        {
            const float send = hi4 ? v[0] : v[1];
            const float recv = __shfl_xor_sync(0xFFFFFFFFu, send, 4);
            v[0] = (hi4 ? v[1] : v[0]) + recv;
        }
        v[0] += __shfl_xor_sync(0xFFFFFFFFu, v[0], 2);
        v[0] += __shfl_xor_sync(0xFFFFFFFFu, v[0], 1);

        if ((lane & 3) == 0)
            scores[(size_t)row * BATCH + (lane >> 2)] = GAMMA_F - v[0];
    };

    u64 A[4], B[4];
    int r = start;
    if (r     < end) loadrow(r,     A);
    if (r + 1 < end) loadrow(r + 1, B);

    while (r < end) {
        u64 NA[4], NB[4];
        if (r + 2 < end) loadrow(r + 2, NA);
        if (r + 3 < end) loadrow(r + 3, NB);

        compute_store(A, r);
        if (r + 1 < end) compute_store(B, r + 1);

#pragma unroll
        for (int i = 0; i < 4; i++) { A[i] = NA[i]; B[i] = NB[i]; }
        r += 2;
    }
}

// ---------------------------------------------------------------------------
// Phase 2: out[b][n] = scores[neg[b][n]*8 + b]. 4 gathers/thread, many blocks.
// ---------------------------------------------------------------------------
__global__ void __launch_bounds__(128)
gather_kernel(const float* __restrict__ scores,
              const int*   __restrict__ neg,
              float*       __restrict__ out,
              int nneg)
{
    const int b = blockIdx.y;
    const int t = blockIdx.x * blockDim.x + threadIdx.x;
    const int n4 = nneg >> 2;
    if (t >= n4) return;

    const int4 idx = reinterpret_cast<const int4*>(neg + (size_t)b * nneg)[t];
    float4 r;
    r.x = scores[(size_t)idx.x * BATCH + b];
    r.y = scores[(size_t)idx.y * BATCH + b];
    r.z = scores[(size_t)idx.z * BATCH + b];
    r.w = scores[(size_t)idx.w * BATCH + b];
    reinterpret_cast<float4*>(out + (size_t)b * nneg)[t] = r;
}

extern "C" void kernel_launch(void* const* d_in, const int* in_sizes, int n_in,
                              void* d_out, int out_size)
{
    const float* ent = (const float*)d_in[0];  // [NE, 256] f32
    const float* rel = (const float*)d_in[1];  // [NR, 256] f32
    const int*   pos = (const int*)d_in[2];    // [B, 3] i32
    const int*   neg = (const int*)d_in[3];    // [B, N] i32
    float*       out = (float*)d_out;          // [B, N] f32

    const int batch = in_sizes[2] / 3;         // 8
    const int nneg  = in_sizes[3] / batch;     // 100000
    const int ne    = in_sizes[0] / HID;       // 100000

    float* scores;
    cudaGetSymbolAddress((void**)&scores, g_scores);

    score_all_kernel<<<296, 256>>>(ent, rel, pos, scores, ne);

    const int n4 = nneg / 4;
    dim3 g2((n4 + 127) / 128, batch);
    gather_kernel<<<g2, 128>>>(scores, neg, out, nneg);
}